// round 2
// baseline (speedup 1.0000x reference)
#include <cuda_runtime.h>
#include <cstdint>
#include <math.h>

// Problem shape
#define S_LEN   512
#define D_HEAD  64
#define BHC     128          // B*H = 8*16
#define NV      3
#define QT      64           // q rows per block
#define N_ELEMS (BHC * S_LEN * S_LEN)        // 33,554,432 attn elements
#define N_MASK_WORDS (N_ELEMS / 32)          // 1,048,576 packed mask words

// Packed dropout keep-mask (bit i of word w -> element w*32+i), scratch in BSS
__device__ uint32_t g_mask[N_MASK_WORDS];

// ---------------------------------------------------------------------------
// Threefry-2x32, key = (0, 42) (jax.random.key(42)), 20 rounds.
// ---------------------------------------------------------------------------
#define TF_R(r) do { x0 += x1; x1 = __funnelshift_l(x1, x1, (r)); x1 ^= x0; } while (0)

__device__ __forceinline__ uint32_t threefry_word(uint32_t c0, uint32_t c1) {
    const uint32_t ks0 = 0u;
    const uint32_t ks1 = 42u;
    const uint32_t ks2 = 0x1BD11BDAu ^ 0u ^ 42u;
    uint32_t x0 = c0 + ks0;
    uint32_t x1 = c1 + ks1;
    TF_R(13); TF_R(15); TF_R(26); TF_R(6);
    x0 += ks1; x1 += ks2 + 1u;
    TF_R(17); TF_R(29); TF_R(16); TF_R(24);
    x0 += ks2; x1 += ks0 + 2u;
    TF_R(13); TF_R(15); TF_R(26); TF_R(6);
    x0 += ks0; x1 += ks1 + 3u;
    TF_R(17); TF_R(29); TF_R(16); TF_R(24);
    x0 += ks1; x1 += ks2 + 4u;
    TF_R(13); TF_R(15); TF_R(26); TF_R(6);
    x0 += ks2; x1 += ks0 + 5u;
    // MASK MODE: jax_threefry_partitionable=True (default since JAX 0.5):
    // counter = uint64 flat index -> (hi, lo); 32-bit output = out0 ^ out1.
    // (Round-1 used out0 alone -> rel_err 0.84. Fallback if still wrong:
    // legacy paired layout out0(i, i+2^24) / out1(i-2^24, i).)
    return x0 ^ x1;
}

__device__ __forceinline__ bool keep_elem(uint32_t bits) {
    // jax.random.uniform: u = bitcast((bits>>9) | 0x3f800000) - 1.0 ; keep = u < 0.65
    float u = __uint_as_float((bits >> 9) | 0x3f800000u) - 1.0f;
    return u < 0.65f;
}

// ---------------------------------------------------------------------------
// Kernel 1: dropout mask generation -> packed bits
// ---------------------------------------------------------------------------
__global__ void maskgen_kernel() {
    uint32_t w = blockIdx.x * blockDim.x + threadIdx.x;
    if (w >= N_MASK_WORDS) return;
    uint32_t base = w * 32u;   // element index < 2^25 -> hi counter word = 0
    uint32_t out = 0u;
#pragma unroll 4
    for (int b = 0; b < 32; b++) {
        uint32_t bits = threefry_word(0u, base + (uint32_t)b);
        if (keep_elem(bits)) out |= (1u << b);
    }
    g_mask[w] = out;
}

// ---------------------------------------------------------------------------
// Kernel 2: fused attention: S = Q K^T * t3 ; softmax ; dropout ; out = P @ V(x3)
// One block per (bh, q-tile of 64). 256 threads.
// Smem: Qs[64d][68] | KVs (K: [64d][68], later V: [64k][196]) | Ss [64q][513] | inv[64]
// ---------------------------------------------------------------------------
#define QS_STRIDE 68
#define VS_STRIDE 196
#define SS_STRIDE 513
#define SM_QS    0
#define SM_KV    (64 * QS_STRIDE)                       // 4352
#define SM_SS    (SM_KV + 64 * VS_STRIDE)               // 4352 + 12544 = 16896
#define SM_INV   (SM_SS + 64 * SS_STRIDE)               // + 32832 = 49728
#define SM_FLOATS (SM_INV + 64)                         // 49792 floats = 199168 B

__global__ void __launch_bounds__(256, 1)
attn_kernel(const float* __restrict__ t0, const float* __restrict__ t1,
            const float* __restrict__ t2, const float* __restrict__ t3,
            float* __restrict__ out) {
    extern __shared__ float sm[];
    float* Qs  = sm + SM_QS;
    float* KVs = sm + SM_KV;
    float* Ss  = sm + SM_SS;
    float* inv = sm + SM_INV;

    const int t  = threadIdx.x;
    const int bh = blockIdx.x >> 3;
    const int q0 = (blockIdx.x & 7) * QT;
    const float scale = *t3;

    const float* Q = t0 + (size_t)bh * S_LEN * D_HEAD + (size_t)q0 * D_HEAD;
    const float* K = t1 + (size_t)bh * S_LEN * D_HEAD;

    // ---- load Q tile transposed: Qs[d][q] ----
#pragma unroll
    for (int r = 0; r < 16; r++) {
        int idx = t + 256 * r;            // 4096 = 64q x 64d
        int q = idx >> 6, d = idx & 63;
        Qs[d * QS_STRIDE + q] = Q[q * D_HEAD + d];
    }
    __syncthreads();

    // ---- S = Q K^T over 8 k-tiles of 64 ----
    const int tq = (t >> 4) * 4;          // 0..60
    const int tk = (t & 15) * 4;          // 0..60
    for (int kt = 0; kt < 8; kt++) {
        const float* Kt = K + (size_t)kt * 64 * D_HEAD;
#pragma unroll
        for (int r = 0; r < 16; r++) {
            int idx = t + 256 * r;
            int k = idx >> 6, d = idx & 63;
            KVs[d * QS_STRIDE + k] = Kt[k * D_HEAD + d];
        }
        __syncthreads();

        float acc[4][4] = {};
#pragma unroll 4
        for (int d = 0; d < 64; d++) {
            float4 qv = *(const float4*)(Qs + d * QS_STRIDE + tq);
            float4 kv = *(const float4*)(KVs + d * QS_STRIDE + tk);
            float qa[4] = {qv.x, qv.y, qv.z, qv.w};
            float ka[4] = {kv.x, kv.y, kv.z, kv.w};
#pragma unroll
            for (int i = 0; i < 4; i++)
#pragma unroll
                for (int j = 0; j < 4; j++)
                    acc[i][j] = fmaf(qa[i], ka[j], acc[i][j]);
        }
#pragma unroll
        for (int i = 0; i < 4; i++)
#pragma unroll
            for (int j = 0; j < 4; j++)
                Ss[(tq + i) * SS_STRIDE + kt * 64 + tk + j] = acc[i][j] * scale;
        __syncthreads();
    }

    // ---- softmax + dropout mask application (in smem) ----
    const int warp = t >> 5, lane = t & 31;
    const uint32_t maskbase = (uint32_t)(bh * S_LEN + q0) * (S_LEN / 32);
#pragma unroll 1
    for (int r = 0; r < 8; r++) {
        int q = warp * 8 + r;
        float* row = Ss + q * SS_STRIDE;
        float m = -INFINITY;
#pragma unroll
        for (int j = 0; j < 16; j++) m = fmaxf(m, row[lane + 32 * j]);
#pragma unroll
        for (int o = 16; o > 0; o >>= 1) m = fmaxf(m, __shfl_xor_sync(0xffffffffu, m, o));
        float ssum = 0.0f;
#pragma unroll
        for (int j = 0; j < 16; j++) {
            float e = __expf(row[lane + 32 * j] - m);
            ssum += e;
            uint32_t mw = g_mask[maskbase + q * 16 + j];
            row[lane + 32 * j] = ((mw >> lane) & 1u) ? e : 0.0f;
        }
#pragma unroll
        for (int o = 16; o > 0; o >>= 1) ssum += __shfl_xor_sync(0xffffffffu, ssum, o);
        if (lane == 0) inv[q] = 1.0f / (ssum * 0.65f);  // fold /(1-p) into normalization
    }
    __syncthreads();

    // ---- out = P @ V for v = 0..2 ----
    const int pq = (t & 15) * 4;          // q sub-tile
    const int d0 = (t >> 4) * 4;          // d sub-tile (0..60)
    float acc[4][NV][4] = {};
    for (int kt = 0; kt < 8; kt++) {
        const float* Vb = t2 + (size_t)bh * NV * S_LEN * D_HEAD + (size_t)kt * 64 * D_HEAD;
#pragma unroll
        for (int r = 0; r < 48; r++) {
            int idx = t + 256 * r;        // 12288 = 64k x 192dv
            int k = idx / 192, dv = idx - k * 192;
            int v = dv >> 6, d = dv & 63;
            KVs[k * VS_STRIDE + dv] = Vb[(size_t)v * S_LEN * D_HEAD + k * D_HEAD + d];
        }
        __syncthreads();
#pragma unroll 2
        for (int k = 0; k < 64; k++) {
            float p[4];
#pragma unroll
            for (int i = 0; i < 4; i++) p[i] = Ss[(pq + i) * SS_STRIDE + kt * 64 + k];
#pragma unroll
            for (int v = 0; v < NV; v++) {
                float4 vv = *(const float4*)(KVs + k * VS_STRIDE + v * 64 + d0);
                float va[4] = {vv.x, vv.y, vv.z, vv.w};
#pragma unroll
                for (int i = 0; i < 4; i++)
#pragma unroll
                    for (int j = 0; j < 4; j++)
                        acc[i][v][j] = fmaf(p[i], va[j], acc[i][v][j]);
            }
        }
        __syncthreads();
    }

    // ---- normalize + write ----
#pragma unroll
    for (int i = 0; i < 4; i++) {
        float s = inv[pq + i];
#pragma unroll
        for (int v = 0; v < NV; v++) {
            float4 o;
            o.x = acc[i][v][0] * s;
            o.y = acc[i][v][1] * s;
            o.z = acc[i][v][2] * s;
            o.w = acc[i][v][3] * s;
            size_t off = (((size_t)bh * NV + v) * S_LEN + (q0 + pq + i)) * D_HEAD + d0;
            *(float4*)(out + off) = o;
        }
    }
}

// ---------------------------------------------------------------------------
extern "C" void kernel_launch(void* const* d_in, const int* in_sizes, int n_in,
                              void* d_out, int out_size) {
    const float* t0 = (const float*)d_in[0];
    const float* t1 = (const float*)d_in[1];
    const float* t2 = (const float*)d_in[2];
    const float* t3 = (const float*)d_in[3];
    float* out = (float*)d_out;

    static bool attr_set = false;
    if (!attr_set) {
        cudaFuncSetAttribute(attn_kernel, cudaFuncAttributeMaxDynamicSharedMemorySize,
                             SM_FLOATS * (int)sizeof(float));
        attr_set = true;
    }

    maskgen_kernel<<<N_MASK_WORDS / 256, 256>>>();
    attn_kernel<<<BHC * (S_LEN / QT), 256, SM_FLOATS * sizeof(float)>>>(t0, t1, t2, t3, out);
}

// round 4
// speedup vs baseline: 1.9775x; 1.9775x over previous
#include <cuda_runtime.h>
#include <cstdint>
#include <math.h>

// Problem shape
#define S_LEN   512
#define D_HEAD  64
#define BHC     128
#define NV      3
#define N_ELEMS (BHC * S_LEN * S_LEN)
#define N_MASK_WORDS (N_ELEMS / 32)

__device__ uint32_t g_mask[N_MASK_WORDS];

// ---------------------------------------------------------------------------
// Threefry-2x32 maskgen (bit-exact per Round 2: partitionable, out0^out1)
// ---------------------------------------------------------------------------
#define TF_R(r) do { x0 += x1; x1 = __funnelshift_l(x1, x1, (r)); x1 ^= x0; } while (0)

__device__ __forceinline__ uint32_t threefry_word(uint32_t c0, uint32_t c1) {
    const uint32_t ks1 = 42u;
    const uint32_t ks2 = 0x1BD11BDAu ^ 42u;
    uint32_t x0 = c0;
    uint32_t x1 = c1 + ks1;
    TF_R(13); TF_R(15); TF_R(26); TF_R(6);
    x0 += ks1; x1 += ks2 + 1u;
    TF_R(17); TF_R(29); TF_R(16); TF_R(24);
    x0 += ks2; x1 += 0u + 2u;
    TF_R(13); TF_R(15); TF_R(26); TF_R(6);
    x0 += 0u; x1 += ks1 + 3u;
    TF_R(17); TF_R(29); TF_R(16); TF_R(24);
    x0 += ks1; x1 += ks2 + 4u;
    TF_R(13); TF_R(15); TF_R(26); TF_R(6);
    x0 += ks2; x1 += 0u + 5u;
    return x0 ^ x1;
}

__device__ __forceinline__ bool keep_elem(uint32_t bits) {
    float u = __uint_as_float((bits >> 9) | 0x3f800000u) - 1.0f;
    return u < 0.65f;
}

__global__ void maskgen_kernel() {
    uint32_t w = blockIdx.x * blockDim.x + threadIdx.x;
    if (w >= N_MASK_WORDS) return;
    uint32_t base = w * 32u;
    uint32_t out = 0u;
#pragma unroll 4
    for (int b = 0; b < 32; b++) {
        if (keep_elem(threefry_word(0u, base + (uint32_t)b))) out |= (1u << b);
    }
    g_mask[w] = out;
}

// ---------------------------------------------------------------------------
// mma.sync helpers (sm_80-level PTX: legal on compute_103 target)
// ---------------------------------------------------------------------------
__device__ __forceinline__ uint32_t smem_u32(const void* p) {
    uint32_t a;
    asm("{ .reg .u64 t; cvta.to.shared.u64 t, %1; cvt.u32.u64 %0, t; }" : "=r"(a) : "l"(p));
    return a;
}
__device__ __forceinline__ float rna_tf32(float x) {
    uint32_t u;
    asm("cvt.rna.tf32.f32 %0, %1;" : "=r"(u) : "f"(x));
    return __uint_as_float(u);
}

#define LDSM4(r0, r1, r2, r3, addr)                                          \
    asm volatile("ldmatrix.sync.aligned.m8n8.x4.shared.b16 {%0,%1,%2,%3}, [%4];" \
        : "=r"(r0), "=r"(r1), "=r"(r2), "=r"(r3) : "r"(addr))

#define MMA8(c, a, b0, b1)                                                   \
    asm volatile("mma.sync.aligned.m16n8k8.row.col.f32.tf32.tf32.f32 "       \
        "{%0,%1,%2,%3}, {%4,%5,%6,%7}, {%8,%9}, {%0,%1,%2,%3};"              \
        : "+f"((c)[0]), "+f"((c)[1]), "+f"((c)[2]), "+f"((c)[3])             \
        : "r"((a)[0]), "r"((a)[1]), "r"((a)[2]), "r"((a)[3]),                \
          "r"(b0), "r"(b1))

// SMEM layout (float offsets), stride 68 floats per row
#define LD   68
#define QHI  0
#define QLO  8704
#define KHI  17408
#define KLO  21760
#define VT   26112
#define PS   39168
#define RS   47872
#define SM_FLOATS 48000   // 192000 bytes

__global__ void __launch_bounds__(256, 1)
attn_mma(const float* __restrict__ t0, const float* __restrict__ t1,
         const float* __restrict__ t2, const float* __restrict__ t3,
         float* __restrict__ out) {
    extern __shared__ float smf[];
    const uint32_t sb = smem_u32(smf);
    const int tid = threadIdx.x, wid = tid >> 5, lane = tid & 31;
    const int g = lane >> 2, i4 = lane & 3;
    const int bh = blockIdx.x >> 2, q0 = (blockIdx.x & 3) << 7;
    const float scale = *t3;

    // warp tiles: MMA1 4Mx2N (32q x 32k), MMA2 2Mx4N (64q x 48d)
    const int qb1 = (wid >> 1) * 32, kb1 = (wid & 1) * 32;
    const int qb2 = (wid >> 2) * 64, db2 = (wid & 3) * 48;

    // ldmatrix lane address components
    const int ar = lane & 15, ac = (lane >> 4) << 2;   // A-pattern (16 rows x 8 cols)
    const int br = lane & 7,  bc = (lane >> 3) << 2;   // B-pattern (8 rows x 16 cols)

    if (tid < 128) smf[RS + tid] = 0.0f;

    // ---- Q [128,64] -> hi/lo ----
    const float* Qg = t0 + ((size_t)bh * S_LEN + q0) * D_HEAD;
#pragma unroll
    for (int i = 0; i < 8; i++) {
        int idx = tid + (i << 8);
        int r = idx >> 4, d4 = (idx & 15) << 2;
        float4 x = *(const float4*)(Qg + r * D_HEAD + d4);
        float4 h, l;
        h.x = rna_tf32(x.x); l.x = rna_tf32(x.x - h.x);
        h.y = rna_tf32(x.y); l.y = rna_tf32(x.y - h.y);
        h.z = rna_tf32(x.z); l.z = rna_tf32(x.z - h.z);
        h.w = rna_tf32(x.w); l.w = rna_tf32(x.w - h.w);
        *(float4*)(smf + QHI + r * LD + d4) = h;
        *(float4*)(smf + QLO + r * LD + d4) = l;
    }

    const float* Kg = t1 + (size_t)bh * S_LEN * D_HEAD;

    auto loadK = [&](int kt) {
#pragma unroll
        for (int i = 0; i < 4; i++) {
            int idx = tid + (i << 8);
            int r = idx >> 4, d4 = (idx & 15) << 2;
            float4 x = *(const float4*)(Kg + (size_t)(kt * 64 + r) * D_HEAD + d4);
            float4 h, l;
            h.x = rna_tf32(x.x); l.x = rna_tf32(x.x - h.x);
            h.y = rna_tf32(x.y); l.y = rna_tf32(x.y - h.y);
            h.z = rna_tf32(x.z); l.z = rna_tf32(x.z - h.z);
            h.w = rna_tf32(x.w); l.w = rna_tf32(x.w - h.w);
            *(float4*)(smf + KHI + r * LD + d4) = h;
            *(float4*)(smf + KLO + r * LD + d4) = l;
        }
    };
    auto loadV = [&](int kt) {   // store V transposed: VT[dglobal][k]
#pragma unroll
        for (int i = 0; i < 12; i++) {
            int idx = tid + (i << 8);
            int v = idx >> 10, rem = idx & 1023;
            int k = rem >> 4, d4 = (rem & 15) << 2;
            float4 x = *(const float4*)(t2 + (((size_t)bh * NV + v) * S_LEN + kt * 64 + k) * D_HEAD + d4);
            int dg = v * 64 + d4;
            smf[VT + (dg + 0) * LD + k] = rna_tf32(x.x);
            smf[VT + (dg + 1) * LD + k] = rna_tf32(x.y);
            smf[VT + (dg + 2) * LD + k] = rna_tf32(x.z);
            smf[VT + (dg + 3) * LD + k] = rna_tf32(x.w);
        }
    };

    loadK(0);
    loadV(0);
    __syncthreads();

    float o[4][6][4];
#pragma unroll
    for (int a = 0; a < 4; a++)
#pragma unroll
        for (int b = 0; b < 6; b++)
#pragma unroll
            for (int c = 0; c < 4; c++) o[a][b][c] = 0.0f;
    float rs4[4] = {0.0f, 0.0f, 0.0f, 0.0f};

    for (int kt = 0; kt < 8; kt++) {
        // ================= MMA1: S[128,64] = Q K^T (3x tf32 split) ========
        float s[2][4][4];
#pragma unroll
        for (int a = 0; a < 2; a++)
#pragma unroll
            for (int b = 0; b < 4; b++)
#pragma unroll
                for (int c = 0; c < 4; c++) s[a][b][c] = 0.0f;

#pragma unroll
        for (int kp = 0; kp < 4; kp++) {
            uint32_t bhi[4][4], blo[4][4];
#pragma unroll
            for (int nt = 0; nt < 4; nt++) {
                uint32_t rowoff = (uint32_t)((kb1 + 8 * nt + br) * LD + kp * 16 + bc);
                uint32_t a1 = sb + ((KHI + rowoff) << 2);
                LDSM4(bhi[nt][0], bhi[nt][1], bhi[nt][2], bhi[nt][3], a1);
                uint32_t a2 = sb + ((KLO + rowoff) << 2);
                LDSM4(blo[nt][0], blo[nt][1], blo[nt][2], blo[nt][3], a2);
            }
#pragma unroll
            for (int sub = 0; sub < 2; sub++) {
                int ks = kp * 2 + sub;
                uint32_t ah[2][4], al[2][4];
#pragma unroll
                for (int mt = 0; mt < 2; mt++) {
                    uint32_t rowoff = (uint32_t)((qb1 + 16 * mt + ar) * LD + ks * 8 + ac);
                    uint32_t aq = sb + ((QHI + rowoff) << 2);
                    LDSM4(ah[mt][0], ah[mt][1], ah[mt][2], ah[mt][3], aq);
                    uint32_t aq2 = sb + ((QLO + rowoff) << 2);
                    LDSM4(al[mt][0], al[mt][1], al[mt][2], al[mt][3], aq2);
                }
#pragma unroll
                for (int mt = 0; mt < 2; mt++)
#pragma unroll
                    for (int nt = 0; nt < 4; nt++) {
                        MMA8(s[mt][nt], ah[mt], bhi[nt][2 * sub], bhi[nt][2 * sub + 1]);
                        MMA8(s[mt][nt], al[mt], bhi[nt][2 * sub], bhi[nt][2 * sub + 1]);
                        MMA8(s[mt][nt], ah[mt], blo[nt][2 * sub], blo[nt][2 * sub + 1]);
                    }
            }
        }

        // ================= softmax + dropout -> P smem =====================
        const uint32_t mrow = (uint32_t)(bh * S_LEN + q0);
#pragma unroll
        for (int mt = 0; mt < 2; mt++)
#pragma unroll
            for (int dr = 0; dr < 2; dr++) {
                int row = qb1 + 16 * mt + 8 * dr + g;
                uint32_t mw = g_mask[(mrow + row) * 16u + (uint32_t)(kt * 2 + (wid & 1))];
                float psum = 0.0f;
#pragma unroll
                for (int nt = 0; nt < 4; nt++) {
                    float e0 = __expf(s[mt][nt][dr * 2 + 0] * scale);
                    float e1 = __expf(s[mt][nt][dr * 2 + 1] * scale);
                    psum += e0 + e1;
                    int bp = 8 * nt + 2 * i4;
                    float p0 = ((mw >> bp) & 1u) ? e0 : 0.0f;
                    float p1 = ((mw >> (bp + 1)) & 1u) ? e1 : 0.0f;
                    float2 pr;
                    pr.x = rna_tf32(p0);
                    pr.y = rna_tf32(p1);
                    *(float2*)(smf + PS + row * LD + kb1 + bp) = pr;
                }
                rs4[mt * 2 + dr] += psum;
            }
        __syncthreads();

        // ================= MMA2: O[128,192] += P V ========================
#pragma unroll
        for (int kp = 0; kp < 4; kp++) {
            uint32_t bv[6][4];
#pragma unroll
            for (int nt = 0; nt < 6; nt++) {
                uint32_t a1 = sb + ((VT + (uint32_t)((db2 + 8 * nt + br) * LD + kp * 16 + bc)) << 2);
                LDSM4(bv[nt][0], bv[nt][1], bv[nt][2], bv[nt][3], a1);
            }
#pragma unroll
            for (int sub = 0; sub < 2; sub++) {
                int ks = kp * 2 + sub;
                uint32_t ap[4][4];
#pragma unroll
                for (int mt = 0; mt < 4; mt++) {
                    uint32_t a1 = sb + ((PS + (uint32_t)((qb2 + 16 * mt + ar) * LD + ks * 8 + ac)) << 2);
                    LDSM4(ap[mt][0], ap[mt][1], ap[mt][2], ap[mt][3], a1);
                }
#pragma unroll
                for (int mt = 0; mt < 4; mt++)
#pragma unroll
                    for (int nt = 0; nt < 6; nt++)
                        MMA8(o[mt][nt], ap[mt], bv[nt][2 * sub], bv[nt][2 * sub + 1]);
            }
        }
        __syncthreads();

        if (kt < 7) {
            loadK(kt + 1);
            loadV(kt + 1);
            __syncthreads();
        }
    }

    // ---- row-sum reduction ----
#pragma unroll
    for (int j = 0; j < 4; j++) {
        float v = rs4[j];
        v += __shfl_xor_sync(0xffffffffu, v, 1);
        v += __shfl_xor_sync(0xffffffffu, v, 2);
        if (i4 == 0) atomicAdd(&smf[RS + qb1 + 16 * (j >> 1) + 8 * (j & 1) + g], v);
    }
    __syncthreads();
    if (tid < 128) smf[RS + tid] = 1.0f / (smf[RS + tid] * 0.65f);
    __syncthreads();

    // ---- epilogue: normalize + store ----
#pragma unroll
    for (int mt = 0; mt < 4; mt++)
#pragma unroll
        for (int dr = 0; dr < 2; dr++) {
            int row = qb2 + 16 * mt + 8 * dr + g;
            float inv = smf[RS + row];
#pragma unroll
            for (int nt = 0; nt < 6; nt++) {
                int col = db2 + 8 * nt + 2 * i4;
                int v = col >> 6, d = col & 63;
                float2 w;
                w.x = o[mt][nt][dr * 2 + 0] * inv;
                w.y = o[mt][nt][dr * 2 + 1] * inv;
                *(float2*)(out + (((size_t)bh * NV + v) * S_LEN + q0 + row) * D_HEAD + d) = w;
            }
        }
}

// ---------------------------------------------------------------------------
extern "C" void kernel_launch(void* const* d_in, const int* in_sizes, int n_in,
                              void* d_out, int out_size) {
    const float* t0 = (const float*)d_in[0];
    const float* t1 = (const float*)d_in[1];
    const float* t2 = (const float*)d_in[2];
    const float* t3 = (const float*)d_in[3];
    float* out = (float*)d_out;

    static bool attr_set = false;
    if (!attr_set) {
        cudaFuncSetAttribute(attn_mma, cudaFuncAttributeMaxDynamicSharedMemorySize,
                             SM_FLOATS * (int)sizeof(float));
        attr_set = true;
    }

    maskgen_kernel<<<N_MASK_WORDS / 256, 256>>>();
    attn_mma<<<BHC * 4, 256, SM_FLOATS * sizeof(float)>>>(t0, t1, t2, t3, out);
}

// round 5
// speedup vs baseline: 2.0318x; 1.0274x over previous
#include <cuda_runtime.h>
#include <cstdint>
#include <math.h>

// Problem shape
#define S_LEN   512
#define D_HEAD  64
#define BHC     128
#define NV      3

// ---------------------------------------------------------------------------
// Threefry-2x32, key (0,42), partitionable fold out0^out1 (bit-exact, R2/R4)
// ---------------------------------------------------------------------------
#define TF_R(r) do { x0 += x1; x1 = __funnelshift_l(x1, x1, (r)); x1 ^= x0; } while (0)

__device__ __forceinline__ uint32_t threefry_word(uint32_t c1) {
    const uint32_t ks1 = 42u;
    const uint32_t ks2 = 0x1BD11BDAu ^ 42u;
    uint32_t x0 = 0u;
    uint32_t x1 = c1 + ks1;
    TF_R(13); TF_R(15); TF_R(26); TF_R(6);
    x0 += ks1; x1 += ks2 + 1u;
    TF_R(17); TF_R(29); TF_R(16); TF_R(24);
    x0 += ks2; x1 += 0u + 2u;
    TF_R(13); TF_R(15); TF_R(26); TF_R(6);
    x0 += 0u; x1 += ks1 + 3u;
    TF_R(17); TF_R(29); TF_R(16); TF_R(24);
    x0 += ks1; x1 += ks2 + 4u;
    TF_R(13); TF_R(15); TF_R(26); TF_R(6);
    x0 += ks2; x1 += 0u + 5u;
    return x0 ^ x1;
}
// keep <=> uniform(bits) < 0.65f <=> bits < 0xA6666600 (exact integer form)
#define KEEP(bits) ((bits) < 0xA6666600u)

// ---------------------------------------------------------------------------
// mma.sync helpers (sm_80-level PTX, legal on compute_103)
// ---------------------------------------------------------------------------
__device__ __forceinline__ uint32_t smem_u32(const void* p) {
    uint32_t a;
    asm("{ .reg .u64 t; cvta.to.shared.u64 t, %1; cvt.u32.u64 %0, t; }" : "=r"(a) : "l"(p));
    return a;
}
__device__ __forceinline__ float rna_tf32(float x) {
    uint32_t u;
    asm("cvt.rna.tf32.f32 %0, %1;" : "=r"(u) : "f"(x));
    return __uint_as_float(u);
}

#define LDSM4(r0, r1, r2, r3, addr)                                          \
    asm volatile("ldmatrix.sync.aligned.m8n8.x4.shared.b16 {%0,%1,%2,%3}, [%4];" \
        : "=r"(r0), "=r"(r1), "=r"(r2), "=r"(r3) : "r"(addr))

#define MMA8(c, a, b0, b1)                                                   \
    asm volatile("mma.sync.aligned.m16n8k8.row.col.f32.tf32.tf32.f32 "       \
        "{%0,%1,%2,%3}, {%4,%5,%6,%7}, {%8,%9}, {%0,%1,%2,%3};"              \
        : "+f"((c)[0]), "+f"((c)[1]), "+f"((c)[2]), "+f"((c)[3])             \
        : "r"((a)[0]), "r"((a)[1]), "r"((a)[2]), "r"((a)[3]),                \
          "r"(b0), "r"(b1))

// SMEM layout (float offsets), row stride 68 floats
#define LD   68
#define QHI  0
#define QLO  8704
#define KHI  17408
#define KLO  21760
#define VT   26112
#define PS   39168
#define RS   47872
#define SM_FLOATS 48000   // 192000 bytes

__global__ void __launch_bounds__(512, 1)
attn_mma(const float* __restrict__ t0, const float* __restrict__ t1,
         const float* __restrict__ t2, const float* __restrict__ t3,
         float* __restrict__ out) {
    extern __shared__ float smf[];
    const uint32_t sb = smem_u32(smf);
    const int tid = threadIdx.x, wid = tid >> 5, lane = tid & 31;
    const int g = lane >> 2, i4 = lane & 3;
    const int bh = blockIdx.x >> 2, q0 = (blockIdx.x & 3) << 7;
    const float scale = *t3;

    // MMA1 warp tile: 16q x 32k ; MMA2 warp tile: 32q x 48d
    const int qb1 = (wid >> 1) << 4, kb1 = (wid & 1) << 5;
    const int qb2 = (wid >> 2) << 5, db2 = (wid & 3) * 48;

    const int ar = lane & 15, ac = (lane >> 4) << 2;   // ldmatrix A pattern
    const int br = lane & 7,  bc = (lane >> 3) << 2;   // ldmatrix B pattern

    if (tid < 128) smf[RS + tid] = 0.0f;

    // ---- Q [128,64] -> hi/lo ----
    const float* Qg = t0 + ((size_t)bh * S_LEN + q0) * D_HEAD;
#pragma unroll
    for (int i = 0; i < 4; i++) {
        int idx = tid + (i << 9);
        int r = idx >> 4, d4 = (idx & 15) << 2;
        float4 x = *(const float4*)(Qg + r * D_HEAD + d4);
        float4 h, l;
        h.x = rna_tf32(x.x); l.x = rna_tf32(x.x - h.x);
        h.y = rna_tf32(x.y); l.y = rna_tf32(x.y - h.y);
        h.z = rna_tf32(x.z); l.z = rna_tf32(x.z - h.z);
        h.w = rna_tf32(x.w); l.w = rna_tf32(x.w - h.w);
        *(float4*)(smf + QHI + r * LD + d4) = h;
        *(float4*)(smf + QLO + r * LD + d4) = l;
    }

    const float* Kg = t1 + (size_t)bh * S_LEN * D_HEAD;
    const float* Vg = t2 + (size_t)bh * NV * S_LEN * D_HEAD;

    // K tile loader: thread handles 2 float4 (r, d4)
    auto storeK = [&](float4 x, int idx) {
        int r = idx >> 4, d4 = (idx & 15) << 2;
        float4 h, l;
        h.x = rna_tf32(x.x); l.x = rna_tf32(x.x - h.x);
        h.y = rna_tf32(x.y); l.y = rna_tf32(x.y - h.y);
        h.z = rna_tf32(x.z); l.z = rna_tf32(x.z - h.z);
        h.w = rna_tf32(x.w); l.w = rna_tf32(x.w - h.w);
        *(float4*)(smf + KHI + r * LD + d4) = h;
        *(float4*)(smf + KLO + r * LD + d4) = l;
    };
    auto ldK = [&](int kt, int idx) {
        int r = idx >> 4, d4 = (idx & 15) << 2;
        return *(const float4*)(Kg + (size_t)(kt * 64 + r) * D_HEAD + d4);
    };
    // V tile loader: VT[d][k], thread handles chunk (d, 4 consecutive k)
    auto loadV = [&](int kt) {
#pragma unroll
        for (int i = 0; i < 6; i++) {
            int c = tid + (i << 9);          // 3072 chunks: 192 d x 16 kgroups
            int kg = c / 192, d = c - kg * 192;
            int v = d >> 6, dl = d & 63;
            const float* p = Vg + (((size_t)v * S_LEN) + kt * 64 + kg * 4) * D_HEAD + dl;
            float4 w;
            w.x = rna_tf32(p[0]);
            w.y = rna_tf32(p[64]);
            w.z = rna_tf32(p[128]);
            w.w = rna_tf32(p[192]);
            *(float4*)(smf + VT + d * LD + kg * 4) = w;
        }
    };

    {   // K(0), V(0)
#pragma unroll
        for (int i = 0; i < 2; i++) storeK(ldK(0, tid + (i << 9)), tid + (i << 9));
        loadV(0);
    }
    __syncthreads();

    float o[2][6][4];
#pragma unroll
    for (int a = 0; a < 2; a++)
#pragma unroll
        for (int b = 0; b < 6; b++)
#pragma unroll
            for (int c = 0; c < 4; c++) o[a][b][c] = 0.0f;
    float rs2[2] = {0.0f, 0.0f};
    const uint32_t rowbase = (uint32_t)(bh * S_LEN + q0);

    for (int kt = 0; kt < 8; kt++) {
        // ============ MMA1: S[128,64] = Q K^T (3x tf32 split) =============
        float s[4][4];
#pragma unroll
        for (int b = 0; b < 4; b++)
#pragma unroll
            for (int c = 0; c < 4; c++) s[b][c] = 0.0f;

#pragma unroll
        for (int kp = 0; kp < 4; kp++) {
            uint32_t bhi[4][4], blo[4][4];
#pragma unroll
            for (int nt = 0; nt < 4; nt++) {
                uint32_t rowoff = (uint32_t)((kb1 + 8 * nt + br) * LD + kp * 16 + bc);
                LDSM4(bhi[nt][0], bhi[nt][1], bhi[nt][2], bhi[nt][3], sb + ((KHI + rowoff) << 2));
                LDSM4(blo[nt][0], blo[nt][1], blo[nt][2], blo[nt][3], sb + ((KLO + rowoff) << 2));
            }
#pragma unroll
            for (int sub = 0; sub < 2; sub++) {
                int ks = kp * 2 + sub;
                uint32_t ah[4], al[4];
                uint32_t rowoff = (uint32_t)((qb1 + ar) * LD + ks * 8 + ac);
                LDSM4(ah[0], ah[1], ah[2], ah[3], sb + ((QHI + rowoff) << 2));
                LDSM4(al[0], al[1], al[2], al[3], sb + ((QLO + rowoff) << 2));
#pragma unroll
                for (int nt = 0; nt < 4; nt++) {
                    MMA8(s[nt], ah, bhi[nt][2 * sub], bhi[nt][2 * sub + 1]);
                    MMA8(s[nt], al, bhi[nt][2 * sub], bhi[nt][2 * sub + 1]);
                    MMA8(s[nt], ah, blo[nt][2 * sub], blo[nt][2 * sub + 1]);
                }
            }
        }

        // ============ softmax + fused threefry dropout -> P ===============
#pragma unroll
        for (int dr = 0; dr < 2; dr++) {
            int row = qb1 + 8 * dr + g;
            uint32_t gidx = (rowbase + (uint32_t)row) * 512u + (uint32_t)(kt * 64 + kb1);
            float psum = 0.0f;
#pragma unroll
            for (int nt = 0; nt < 4; nt++) {
                uint32_t c0 = gidx + (uint32_t)(8 * nt + 2 * i4);
                float e0 = __expf(s[nt][dr * 2 + 0] * scale);
                float e1 = __expf(s[nt][dr * 2 + 1] * scale);
                psum += e0 + e1;
                float2 pr;
                pr.x = rna_tf32(KEEP(threefry_word(c0)) ? e0 : 0.0f);
                pr.y = rna_tf32(KEEP(threefry_word(c0 + 1u)) ? e1 : 0.0f);
                *(float2*)(smf + PS + row * LD + kb1 + 8 * nt + 2 * i4) = pr;
            }
            rs2[dr] += psum;
        }
        __syncthreads();   // barrier 1: P visible; K smem free (MMA1 done)

        // prefetch K(kt+1) into registers (hidden under MMA2)
        float4 kreg0, kreg1;
        if (kt < 7) {
            kreg0 = ldK(kt + 1, tid);
            kreg1 = ldK(kt + 1, tid + 512);
        }

        // ============ MMA2: O[128,192] += P V ============================
#pragma unroll
        for (int kp = 0; kp < 4; kp++) {
            uint32_t bv[6][4];
#pragma unroll
            for (int nt = 0; nt < 6; nt++) {
                uint32_t rowoff = (uint32_t)((db2 + 8 * nt + br) * LD + kp * 16 + bc);
                LDSM4(bv[nt][0], bv[nt][1], bv[nt][2], bv[nt][3], sb + ((VT + rowoff) << 2));
            }
#pragma unroll
            for (int sub = 0; sub < 2; sub++) {
                int ks = kp * 2 + sub;
                uint32_t ap[2][4];
#pragma unroll
                for (int mt = 0; mt < 2; mt++) {
                    uint32_t rowoff = (uint32_t)((qb2 + 16 * mt + ar) * LD + ks * 8 + ac);
                    LDSM4(ap[mt][0], ap[mt][1], ap[mt][2], ap[mt][3], sb + ((PS + rowoff) << 2));
                }
#pragma unroll
                for (int mt = 0; mt < 2; mt++)
#pragma unroll
                    for (int nt = 0; nt < 6; nt++)
                        MMA8(o[mt][nt], ap[mt], bv[nt][2 * sub], bv[nt][2 * sub + 1]);
            }
        }

        if (kt < 7) {
            storeK(kreg0, tid);
            storeK(kreg1, tid + 512);
        }
        __syncthreads();   // barrier 2: MMA2 smem reads done; K(kt+1) visible

        if (kt < 7) loadV(kt + 1);   // overlaps next MMA1; ordered by barrier 1
    }

    // ---- row-sum reduction (denominator includes dropped elems) ----
#pragma unroll
    for (int dr = 0; dr < 2; dr++) {
        float v = rs2[dr];
        v += __shfl_xor_sync(0xffffffffu, v, 1);
        v += __shfl_xor_sync(0xffffffffu, v, 2);
        if (i4 == 0) atomicAdd(&smf[RS + qb1 + 8 * dr + g], v);
    }
    __syncthreads();
    if (tid < 128) smf[RS + tid] = 1.0f / (smf[RS + tid] * 0.65f);
    __syncthreads();

    // ---- epilogue: normalize + store ----
#pragma unroll
    for (int mt = 0; mt < 2; mt++)
#pragma unroll
        for (int dr = 0; dr < 2; dr++) {
            int row = qb2 + 16 * mt + 8 * dr + g;
            float inv = smf[RS + row];
#pragma unroll
            for (int nt = 0; nt < 6; nt++) {
                int col = db2 + 8 * nt + 2 * i4;
                int v = col >> 6, d = col & 63;
                float2 w;
                w.x = o[mt][nt][dr * 2 + 0] * inv;
                w.y = o[mt][nt][dr * 2 + 1] * inv;
                *(float2*)(out + (((size_t)bh * NV + v) * S_LEN + q0 + row) * D_HEAD + d) = w;
            }
        }
}

// ---------------------------------------------------------------------------
extern "C" void kernel_launch(void* const* d_in, const int* in_sizes, int n_in,
                              void* d_out, int out_size) {
    const float* t0 = (const float*)d_in[0];
    const float* t1 = (const float*)d_in[1];
    const float* t2 = (const float*)d_in[2];
    const float* t3 = (const float*)d_in[3];
    float* out = (float*)d_out;

    static bool attr_set = false;
    if (!attr_set) {
        cudaFuncSetAttribute(attn_mma, cudaFuncAttributeMaxDynamicSharedMemorySize,
                             SM_FLOATS * (int)sizeof(float));
        attr_set = true;
    }

    attn_mma<<<BHC * 4, 512, SM_FLOATS * sizeof(float)>>>(t0, t1, t2, t3, out);
}